// round 8
// baseline (speedup 1.0000x reference)
#include <cuda_runtime.h>
#include <cuda_fp16.h>
#include <cstdint>

#define L 2304
#define NBATCH 4
#define CIN 512
#define HCH 64
#define NH 8
#define NNH (NBATCH * NH)        // 32
#define NQT 18                   // q tiles of 128
#define NCHUNK 18                // key chunks of 128

// scratch (no cudaMalloc allowed)
__device__ float g_qkv[NBATCH * 192 * L];        // [n][192][L] fp32
__device__ float g_o[NBATCH * HCH * L];          // [n][64][L]
__device__ float g_vpad[NBATCH * HCH * 2500];    // V with 1-px zero halo [n][ic][50*50]
__device__ __half g_qh[NNH * L * 8];             // [nh][q][8]  (scaled)
__device__ __half g_kh[NNH * L * 8];             // [nh][k][8]
__device__ __half g_vh[NNH * 16 * L];            // [nh][dim16][k], plane8=ones

#define HMMA(c0, c1, c2, c3, a0, a1, a2, a3, b0, b1) \
    asm volatile("mma.sync.aligned.m16n8k16.row.col.f32.f16.f16.f32 " \
        "{%0,%1,%2,%3}, {%4,%5,%6,%7}, {%8,%9}, {%0,%1,%2,%3};" \
        : "+f"(c0), "+f"(c1), "+f"(c2), "+f"(c3) \
        : "r"(a0), "r"(a1), "r"(a2), "r"(a3), "r"(b0), "r"(b1))

// ============================================================
// GEMM with bias (qkv / res 1x1 convs)
// ============================================================
__global__ void __launch_bounds__(256) gemm_bias_kernel(
    const float* __restrict__ A, const float* __restrict__ B,
    const float* __restrict__ bias, float* __restrict__ C,
    int M, int Kdim)
{
    __shared__ float As[16][68];
    __shared__ float Bs[16][132];
    int n  = blockIdx.z;
    int m0 = blockIdx.y * 64;
    int l0 = blockIdx.x * 128;
    int t  = threadIdx.x;
    int tm = t >> 4, tn = t & 15;
    const float* Bn = B + (size_t)n * Kdim * L;

    float acc[4][8];
#pragma unroll
    for (int i = 0; i < 4; i++)
#pragma unroll
        for (int j = 0; j < 8; j++) acc[i][j] = 0.f;

    for (int k0 = 0; k0 < Kdim; k0 += 16) {
        {
            int m = t >> 2, kk = (t & 3) * 4;
            float4 a = *(const float4*)(A + (size_t)(m0 + m) * Kdim + k0 + kk);
            As[kk + 0][m] = a.x; As[kk + 1][m] = a.y;
            As[kk + 2][m] = a.z; As[kk + 3][m] = a.w;
        }
        {
            int kk = t >> 4;
            const float* src = Bn + (size_t)(k0 + kk) * L + l0;
            float4 b0 = *(const float4*)(src + tn * 4);
            float4 b1 = *(const float4*)(src + 64 + tn * 4);
            *(float4*)&Bs[kk][tn * 4] = b0;
            *(float4*)&Bs[kk][64 + tn * 4] = b1;
        }
        __syncthreads();
#pragma unroll
        for (int kk = 0; kk < 16; kk++) {
            float4 a4 = *(const float4*)&As[kk][tm * 4];
            float4 b0 = *(const float4*)&Bs[kk][tn * 4];
            float4 b1 = *(const float4*)&Bs[kk][64 + tn * 4];
            float ar[4] = {a4.x, a4.y, a4.z, a4.w};
            float br[8] = {b0.x, b0.y, b0.z, b0.w, b1.x, b1.y, b1.z, b1.w};
#pragma unroll
            for (int i = 0; i < 4; i++)
#pragma unroll
                for (int j = 0; j < 8; j++)
                    acc[i][j] = fmaf(ar[i], br[j], acc[i][j]);
        }
        __syncthreads();
    }

#pragma unroll
    for (int i = 0; i < 4; i++) {
        int m = m0 + tm * 4 + i;
        float bb = bias[m];
        float* dst = C + ((size_t)n * M + m) * L + l0;
        float4 r0 = make_float4(acc[i][0] + bb, acc[i][1] + bb,
                                acc[i][2] + bb, acc[i][3] + bb);
        float4 r1 = make_float4(acc[i][4] + bb, acc[i][5] + bb,
                                acc[i][6] + bb, acc[i][7] + bb);
        *(float4*)(dst + tn * 4) = r0;
        *(float4*)(dst + 64 + tn * 4) = r1;
    }
}

// ============================================================
// Convert fp32 qkv -> fp16 fragment images + padded fp32 V image.
// ============================================================
#define NT_Q (NNH * L)
#define NT_K (NNH * L)
#define NT_V (NNH * 16 * (L / 8))
#define NT_P (NBATCH * HCH * 50)

__global__ void __launch_bounds__(256) convert_kernel()
{
    const float QS = 0.35355339059327373f * 1.4426950408889634f;
    int id = blockIdx.x * 256 + threadIdx.x;

    if (id < NT_Q) {
        int nh = id / L, q = id - nh * L;
        int n = nh >> 3, h = nh & 7;
        const float* src = g_qkv + ((size_t)n * 192 + h * 24) * L + q;
        uint32_t w[4];
#pragma unroll
        for (int j = 0; j < 4; j++) {
            __half2 h2 = __floats2half2_rn(src[(size_t)(2 * j) * L] * QS,
                                           src[(size_t)(2 * j + 1) * L] * QS);
            w[j] = *(uint32_t*)&h2;
        }
        ((uint4*)g_qh)[id] = make_uint4(w[0], w[1], w[2], w[3]);
        return;
    }
    id -= NT_Q;
    if (id < NT_K) {
        int nh = id / L, k = id - nh * L;
        int n = nh >> 3, h = nh & 7;
        const float* src = g_qkv + ((size_t)n * 192 + h * 24 + 8) * L + k;
        uint32_t w[4];
#pragma unroll
        for (int j = 0; j < 4; j++) {
            __half2 h2 = __floats2half2_rn(src[(size_t)(2 * j) * L],
                                           src[(size_t)(2 * j + 1) * L]);
            w[j] = *(uint32_t*)&h2;
        }
        ((uint4*)g_kh)[id] = make_uint4(w[0], w[1], w[2], w[3]);
        return;
    }
    id -= NT_K;
    if (id < NT_V) {
        int nh = id / (16 * (L / 8));
        int rem = id - nh * 16 * (L / 8);
        int dim = rem / (L / 8);
        int blk = rem - dim * (L / 8);
        uint4 out;
        if (dim < 8) {
            int n = nh >> 3, h = nh & 7;
            const float* src = g_qkv + ((size_t)n * 192 + h * 24 + 16 + dim) * L + blk * 8;
            float4 f0 = *(const float4*)src;
            float4 f1 = *(const float4*)(src + 4);
            __half2 a = __floats2half2_rn(f0.x, f0.y);
            __half2 b = __floats2half2_rn(f0.z, f0.w);
            __half2 c = __floats2half2_rn(f1.x, f1.y);
            __half2 d = __floats2half2_rn(f1.z, f1.w);
            out = make_uint4(*(uint32_t*)&a, *(uint32_t*)&b, *(uint32_t*)&c, *(uint32_t*)&d);
        } else if (dim == 8) {
            out = make_uint4(0x3C003C00u, 0x3C003C00u, 0x3C003C00u, 0x3C003C00u);
        } else {
            out = make_uint4(0, 0, 0, 0);
        }
        ((uint4*)g_vh)[(size_t)(nh * 16 + dim) * (L / 8) + blk] = out;
        return;
    }
    id -= NT_V;
    if (id < NT_P) {
        int n = id / (HCH * 50);
        int rem = id - n * HCH * 50;
        int ic = rem / 50;
        int yp = rem - ic * 50;
        float* dst = g_vpad + ((size_t)n * HCH + ic) * 2500 + yp * 50;
        if (yp == 0 || yp == 49) {
#pragma unroll
            for (int i = 0; i < 50; i++) dst[i] = 0.f;
        } else {
            int c = (ic >> 3) * 24 + 16 + (ic & 7);   // V channel in qkv
            const float* src = g_qkv + ((size_t)n * 192 + c) * L + (yp - 1) * 48;
            dst[0] = 0.f;
#pragma unroll 8
            for (int i = 0; i < 48; i++) dst[1 + i] = src[i];
            dst[49] = 0.f;
        }
    }
}

// ============================================================
// Attention via HMMA m16n8k16 (f16 in, f32 accum).
// grid = 576 (nh * 18 q-tiles), 256 threads = 8 warps x 16 q-rows.
// Pad dim 8 computes (S - 9) for free; clamp via min.f16x2 at 15.
// V plane 8 = ones => ssum in fp32. PV accumulators split even/odd-s
// for 2x ILP on the HMMA accumulate chains.
// ============================================================
__global__ void __launch_bounds__(256) attn_hmma_kernel()
{
    __shared__ uint32_t sK[2][512];        // [buf][key*4 + dimpair]
    __shared__ uint32_t sV[2][16 * 68];    // [buf][plane*68 + keyword]
    int t = threadIdx.x, wid = t >> 5, lane = t & 31;
    int bid = blockIdx.x;
    int qt = bid % NQT;
    int nh = bid / NQT;
    int r = lane >> 2, cq = lane & 3;

    const uint32_t* kg = (const uint32_t*)g_kh + (size_t)nh * L * 4;
    const uint32_t* vg = (const uint32_t*)g_vh + (size_t)nh * 16 * (L / 2);

    // Q fragments (constant over chunks)
    int q0 = qt * 128 + wid * 16;
    const uint32_t* qgp = (const uint32_t*)g_qh + (size_t)(nh * L + q0) * 4;
    uint32_t qa0 = qgp[r * 4 + cq];
    uint32_t qa1 = qgp[(r + 8) * 4 + cq];
    // shift trick: A[row][dim8] = -9 (half 0xC880), B[dim8][n] = 1 (0x3C00)
    uint32_t qa2 = (cq == 0) ? 0x0000C880u : 0u;
    uint32_t kb1 = (cq == 0) ? 0x00003C00u : 0u;
    const uint32_t C15 = 0x4B804B80u;   // (15.0, 15.0) f16x2

    int pl = t >> 4, qw = t & 15;

    // preload chunk 0
    uint2 kreg = ((const uint2*)kg)[t];
    uint4 vreg = *(const uint4*)(vg + (size_t)pl * (L / 2) + qw * 4);
    ((uint2*)sK[0])[t] = kreg;
    *(uint4*)&sV[0][pl * 68 + qw * 4] = vreg;
    __syncthreads();

    float o0[2][4], o1[2][4];
#pragma unroll
    for (int i = 0; i < 4; i++) {
        o0[0][i] = 0.f; o0[1][i] = 0.f;
        o1[0][i] = 0.f; o1[1][i] = 0.f;
    }

    for (int c = 0; c < NCHUNK; c++) {
        int cur = c & 1;
        if (c + 1 < NCHUNK) {   // register-staged prefetch
            kreg = ((const uint2*)(kg + (size_t)(c + 1) * 512))[t];
            vreg = *(const uint4*)(vg + (size_t)pl * (L / 2) + (c + 1) * 64 + qw * 4);
        }

        uint32_t pa[16], pb[16];
#pragma unroll
        for (int j = 0; j < 16; j++) {
            uint32_t kb = sK[cur][j * 32 + r * 4 + cq];
            float s0 = 0.f, s1 = 0.f, s2 = 0.f, s3 = 0.f;
            HMMA(s0, s1, s2, s3, qa0, qa1, qa2, qa2, kb, kb1);
            uint32_t x, y;
            asm("cvt.rn.f16x2.f32 %0, %1, %2;" : "=r"(x) : "f"(s1), "f"(s0));
            asm("min.f16x2 %0, %0, %1;" : "+r"(x) : "r"(C15));
            asm("ex2.approx.f16x2 %0, %1;" : "=r"(x) : "r"(x));
            asm("cvt.rn.f16x2.f32 %0, %1, %2;" : "=r"(y) : "f"(s3), "f"(s2));
            asm("min.f16x2 %0, %0, %1;" : "+r"(y) : "r"(C15));
            asm("ex2.approx.f16x2 %0, %1;" : "=r"(y) : "r"(y));
            pa[j] = x;
            pb[j] = y;
        }

#pragma unroll
        for (int s = 0; s < 8; s++) {
            int ss = s & 1;
            uint32_t b0 = sV[cur][r * 68 + s * 8 + cq];
            uint32_t b1 = sV[cur][r * 68 + s * 8 + cq + 4];
            HMMA(o0[ss][0], o0[ss][1], o0[ss][2], o0[ss][3],
                 pa[2 * s], pb[2 * s], pa[2 * s + 1], pb[2 * s + 1], b0, b1);
            uint32_t b2 = sV[cur][(r + 8) * 68 + s * 8 + cq];
            uint32_t b3 = sV[cur][(r + 8) * 68 + s * 8 + cq + 4];
            HMMA(o1[ss][0], o1[ss][1], o1[ss][2], o1[ss][3],
                 pa[2 * s], pb[2 * s], pa[2 * s + 1], pb[2 * s + 1], b2, b3);
        }

        if (c + 1 < NCHUNK) {
            int nxt = cur ^ 1;
            ((uint2*)sK[nxt])[t] = kreg;
            *(uint4*)&sV[nxt][pl * 68 + qw * 4] = vreg;
        }
        __syncthreads();
    }

    // fold split accumulators; ssum lives in dim-8 column (cq==0 lanes)
    float sslp = o1[0][0] + o1[1][0];
    float sshp = o1[0][2] + o1[1][2];
    float ss_lo = __shfl_sync(0xffffffffu, sslp, lane & ~3);
    float ss_hi = __shfl_sync(0xffffffffu, sshp, lane & ~3);
    float inv_lo = 1.f / fmaxf(ss_lo, 1e-30f);
    float inv_hi = 1.f / fmaxf(ss_hi, 1e-30f);

    int n = nh >> 3, h = nh & 7;
    float* dst = g_o + ((size_t)n * HCH + h * 8 + cq * 2) * L + q0 + r;
    dst[0]     = (o0[0][0] + o0[1][0]) * inv_lo;
    dst[8]     = (o0[0][2] + o0[1][2]) * inv_hi;
    dst[L]     = (o0[0][1] + o0[1][1]) * inv_lo;
    dst[L + 8] = (o0[0][3] + o0[1][3]) * inv_hi;
}

// ============================================================
// Pos 3x3 conv as GEMM over padded V image (no gather, no bounds).
// CTA = (n, image row y): M=64 oc, N=48 px, K=576 in (tap, ic) order.
// B rows are contiguous 48-float slices of g_vpad at (y+dy)*50+dx.
// grid (48,1,4) = 192 CTAs; register-prefetch double buffering.
// ============================================================
__global__ void __launch_bounds__(256) pos_gemm_kernel(
    const float* __restrict__ pw, const float* __restrict__ pb)
{
    __shared__ float As[16][68];
    __shared__ float Bs[16][52];
    int n = blockIdx.z;
    int y = blockIdx.x;
    int t = threadIdx.x;
    int tm = t >> 4, tn = t & 15;
    const float* vp = g_vpad + (size_t)n * HCH * 2500;

    int am = t >> 2;          // oc for A loads
    int ak = (t & 3) * 4;     // kk base for A loads

    float aP[4], bP[3];
    {   // prefetch k0 = 0 (tap 0: dy=0, dx=0)
#pragma unroll
        for (int i = 0; i < 4; i++)
            aP[i] = pw[(size_t)(am * 64 + ak + i) * 9 + 0];
        int rowoff = y * 50;
#pragma unroll
        for (int i = 0; i < 3; i++) {
            int e = i * 256 + t;
            int rk = e / 48, cl = e - rk * 48;
            bP[i] = vp[(size_t)rk * 2500 + rowoff + cl];
        }
    }

    float acc[4][3];
#pragma unroll
    for (int i = 0; i < 4; i++) { acc[i][0] = 0.f; acc[i][1] = 0.f; acc[i][2] = 0.f; }

    for (int k0 = 0; k0 < 576; k0 += 16) {
        // commit prefetched tile
#pragma unroll
        for (int i = 0; i < 4; i++) As[ak + i][am] = aP[i];
#pragma unroll
        for (int i = 0; i < 3; i++) {
            int e = i * 256 + t;
            int rk = e / 48, cl = e - rk * 48;
            Bs[rk][cl] = bP[i];
        }
        __syncthreads();

        int k1 = k0 + 16;
        if (k1 < 576) {   // prefetch next (overlaps compute)
            int tap = k1 >> 6, ic0 = k1 & 63;
            int dy = tap / 3, dx = tap - dy * 3;
#pragma unroll
            for (int i = 0; i < 4; i++)
                aP[i] = pw[(size_t)(am * 64 + ic0 + ak + i) * 9 + tap];
            int rowoff = (y + dy) * 50 + dx;
#pragma unroll
            for (int i = 0; i < 3; i++) {
                int e = i * 256 + t;
                int rk = e / 48, cl = e - rk * 48;
                bP[i] = vp[(size_t)(ic0 + rk) * 2500 + rowoff + cl];
            }
        }

#pragma unroll
        for (int kk = 0; kk < 16; kk++) {
            float4 a4 = *(const float4*)&As[kk][tm * 4];
            float b0 = Bs[kk][tn * 3];
            float b1 = Bs[kk][tn * 3 + 1];
            float b2 = Bs[kk][tn * 3 + 2];
            acc[0][0] = fmaf(a4.x, b0, acc[0][0]);
            acc[0][1] = fmaf(a4.x, b1, acc[0][1]);
            acc[0][2] = fmaf(a4.x, b2, acc[0][2]);
            acc[1][0] = fmaf(a4.y, b0, acc[1][0]);
            acc[1][1] = fmaf(a4.y, b1, acc[1][1]);
            acc[1][2] = fmaf(a4.y, b2, acc[1][2]);
            acc[2][0] = fmaf(a4.z, b0, acc[2][0]);
            acc[2][1] = fmaf(a4.z, b1, acc[2][1]);
            acc[2][2] = fmaf(a4.z, b2, acc[2][2]);
            acc[3][0] = fmaf(a4.w, b0, acc[3][0]);
            acc[3][1] = fmaf(a4.w, b1, acc[3][1]);
            acc[3][2] = fmaf(a4.w, b2, acc[3][2]);
        }
        __syncthreads();
    }

#pragma unroll
    for (int i = 0; i < 4; i++) {
        int oc = tm * 4 + i;
        float bb = pb[oc];
        float* dst = g_o + ((size_t)n * HCH + oc) * L + y * 48 + tn * 3;
        dst[0] += acc[i][0] + bb;
        dst[1] += acc[i][1] + bb;
        dst[2] += acc[i][2] + bb;
    }
}

// ============================================================
extern "C" void kernel_launch(void* const* d_in, const int* in_sizes, int n_in,
                              void* d_out, int out_size)
{
    const float* x     = (const float*)d_in[0];
    const float* qkv_w = (const float*)d_in[1];
    const float* qkv_b = (const float*)d_in[2];
    const float* pos_w = (const float*)d_in[3];
    const float* pos_b = (const float*)d_in[4];
    const float* res_w = (const float*)d_in[5];
    const float* res_b = (const float*)d_in[6];
    float* out = (float*)d_out;

    float* qkv_ptr = nullptr;
    float* o_ptr   = nullptr;
    cudaGetSymbolAddress((void**)&qkv_ptr, g_qkv);
    cudaGetSymbolAddress((void**)&o_ptr, g_o);

    // K1: qkv 1x1 conv as GEMM
    gemm_bias_kernel<<<dim3(18, 3, NBATCH), 256>>>(qkv_w, x, qkv_b, qkv_ptr, 192, CIN);

    // K2: fp32 -> fp16 fragment images + padded V image
    {
        int total = NT_Q + NT_K + NT_V + NT_P;
        convert_kernel<<<(total + 255) / 256, 256>>>();
    }

    // K3: attention (HMMA tensor cores)
    attn_hmma_kernel<<<NNH * NQT, 256>>>();

    // K4: pos conv as clean GEMM over padded image, accumulate into g_o
    pos_gemm_kernel<<<dim3(48, 1, NBATCH), 256>>>(pos_w, pos_b);

    // K5: res 1x1 conv as GEMM
    gemm_bias_kernel<<<dim3(18, 8, NBATCH), 256>>>(res_w, o_ptr, res_b, out, 512, HCH);
}

// round 9
// speedup vs baseline: 1.2116x; 1.2116x over previous
#include <cuda_runtime.h>
#include <cuda_fp16.h>
#include <cstdint>

#define L 2304
#define NBATCH 4
#define CIN 512
#define HCH 64
#define NH 8
#define NNH (NBATCH * NH)        // 32
#define NQT 18                   // q tiles of 128
#define NCHUNK 18                // key chunks of 128

// scratch (no cudaMalloc allowed)
__device__ float g_qkv[NBATCH * 192 * L];        // [n][192][L] fp32
__device__ float g_o[NBATCH * HCH * L];          // [n][64][L]
__device__ __half g_qh[NNH * L * 8];             // [nh][q][8]  (scaled)
__device__ __half g_kh[NNH * L * 8];             // [nh][k][8]
__device__ __half g_vh[NNH * 16 * L];            // [nh][dim16][k], plane8=ones

#define HMMA16(c0, c1, c2, c3, a0, a1, a2, a3, b0, b1) \
    asm volatile("mma.sync.aligned.m16n8k16.row.col.f32.f16.f16.f32 " \
        "{%0,%1,%2,%3}, {%4,%5,%6,%7}, {%8,%9}, {%0,%1,%2,%3};" \
        : "+f"(c0), "+f"(c1), "+f"(c2), "+f"(c3) \
        : "r"(a0), "r"(a1), "r"(a2), "r"(a3), "r"(b0), "r"(b1))

#define HMMA8(c0, c1, c2, c3, a0, a1, b0) \
    asm volatile("mma.sync.aligned.m16n8k8.row.col.f32.f16.f16.f32 " \
        "{%0,%1,%2,%3}, {%4,%5}, {%6}, {%0,%1,%2,%3};" \
        : "+f"(c0), "+f"(c1), "+f"(c2), "+f"(c3) \
        : "r"(a0), "r"(a1), "r"(b0))

// ============================================================
// GEMM with bias (qkv / res 1x1 convs)
// ============================================================
__global__ void __launch_bounds__(256) gemm_bias_kernel(
    const float* __restrict__ A, const float* __restrict__ B,
    const float* __restrict__ bias, float* __restrict__ C,
    int M, int Kdim)
{
    __shared__ float As[16][68];
    __shared__ float Bs[16][132];
    int n  = blockIdx.z;
    int m0 = blockIdx.y * 64;
    int l0 = blockIdx.x * 128;
    int t  = threadIdx.x;
    int tm = t >> 4, tn = t & 15;
    const float* Bn = B + (size_t)n * Kdim * L;

    float acc[4][8];
#pragma unroll
    for (int i = 0; i < 4; i++)
#pragma unroll
        for (int j = 0; j < 8; j++) acc[i][j] = 0.f;

    for (int k0 = 0; k0 < Kdim; k0 += 16) {
        {
            int m = t >> 2, kk = (t & 3) * 4;
            float4 a = *(const float4*)(A + (size_t)(m0 + m) * Kdim + k0 + kk);
            As[kk + 0][m] = a.x; As[kk + 1][m] = a.y;
            As[kk + 2][m] = a.z; As[kk + 3][m] = a.w;
        }
        {
            int kk = t >> 4;
            const float* src = Bn + (size_t)(k0 + kk) * L + l0;
            float4 b0 = *(const float4*)(src + tn * 4);
            float4 b1 = *(const float4*)(src + 64 + tn * 4);
            *(float4*)&Bs[kk][tn * 4] = b0;
            *(float4*)&Bs[kk][64 + tn * 4] = b1;
        }
        __syncthreads();
#pragma unroll
        for (int kk = 0; kk < 16; kk++) {
            float4 a4 = *(const float4*)&As[kk][tm * 4];
            float4 b0 = *(const float4*)&Bs[kk][tn * 4];
            float4 b1 = *(const float4*)&Bs[kk][64 + tn * 4];
            float ar[4] = {a4.x, a4.y, a4.z, a4.w};
            float br[8] = {b0.x, b0.y, b0.z, b0.w, b1.x, b1.y, b1.z, b1.w};
#pragma unroll
            for (int i = 0; i < 4; i++)
#pragma unroll
                for (int j = 0; j < 8; j++)
                    acc[i][j] = fmaf(ar[i], br[j], acc[i][j]);
        }
        __syncthreads();
    }

#pragma unroll
    for (int i = 0; i < 4; i++) {
        int m = m0 + tm * 4 + i;
        float bb = bias[m];
        float* dst = C + ((size_t)n * M + m) * L + l0;
        float4 r0 = make_float4(acc[i][0] + bb, acc[i][1] + bb,
                                acc[i][2] + bb, acc[i][3] + bb);
        float4 r1 = make_float4(acc[i][4] + bb, acc[i][5] + bb,
                                acc[i][6] + bb, acc[i][7] + bb);
        *(float4*)(dst + tn * 4) = r0;
        *(float4*)(dst + 64 + tn * 4) = r1;
    }
}

// ============================================================
// Convert fp32 qkv -> fp16 fragment-friendly images.
// ============================================================
#define NT_Q (NNH * L)
#define NT_K (NNH * L)
#define NT_V (NNH * 16 * (L / 8))

__global__ void __launch_bounds__(256) convert_kernel()
{
    const float QS = 0.35355339059327373f * 1.4426950408889634f;
    int id = blockIdx.x * 256 + threadIdx.x;

    if (id < NT_Q) {
        int nh = id / L, q = id - nh * L;
        int n = nh >> 3, h = nh & 7;
        const float* src = g_qkv + ((size_t)n * 192 + h * 24) * L + q;
        uint32_t w[4];
#pragma unroll
        for (int j = 0; j < 4; j++) {
            __half2 h2 = __floats2half2_rn(src[(size_t)(2 * j) * L] * QS,
                                           src[(size_t)(2 * j + 1) * L] * QS);
            w[j] = *(uint32_t*)&h2;
        }
        ((uint4*)g_qh)[id] = make_uint4(w[0], w[1], w[2], w[3]);
        return;
    }
    id -= NT_Q;
    if (id < NT_K) {
        int nh = id / L, k = id - nh * L;
        int n = nh >> 3, h = nh & 7;
        const float* src = g_qkv + ((size_t)n * 192 + h * 24 + 8) * L + k;
        uint32_t w[4];
#pragma unroll
        for (int j = 0; j < 4; j++) {
            __half2 h2 = __floats2half2_rn(src[(size_t)(2 * j) * L],
                                           src[(size_t)(2 * j + 1) * L]);
            w[j] = *(uint32_t*)&h2;
        }
        ((uint4*)g_kh)[id] = make_uint4(w[0], w[1], w[2], w[3]);
        return;
    }
    id -= NT_K;
    if (id < NT_V) {
        int nh = id / (16 * (L / 8));
        int rem = id - nh * 16 * (L / 8);
        int dim = rem / (L / 8);
        int blk = rem - dim * (L / 8);
        uint4 out;
        if (dim < 8) {
            int n = nh >> 3, h = nh & 7;
            const float* src = g_qkv + ((size_t)n * 192 + h * 24 + 16 + dim) * L + blk * 8;
            float4 f0 = *(const float4*)src;
            float4 f1 = *(const float4*)(src + 4);
            __half2 a = __floats2half2_rn(f0.x, f0.y);
            __half2 b = __floats2half2_rn(f0.z, f0.w);
            __half2 c = __floats2half2_rn(f1.x, f1.y);
            __half2 d = __floats2half2_rn(f1.z, f1.w);
            out = make_uint4(*(uint32_t*)&a, *(uint32_t*)&b, *(uint32_t*)&c, *(uint32_t*)&d);
        } else if (dim == 8) {
            out = make_uint4(0x3C003C00u, 0x3C003C00u, 0x3C003C00u, 0x3C003C00u);
        } else {
            out = make_uint4(0, 0, 0, 0);
        }
        ((uint4*)g_vh)[(size_t)(nh * 16 + dim) * (L / 8) + blk] = out;
    }
}

// ============================================================
// Attention via HMMA (f16 in, f32 accum).
// grid = 576 (nh * 18 q-tiles), 256 threads = 8 warps x 16 q-rows.
// S-MMA = m16n8k8 (K=8 dims exactly), accumulator init -9 gives the
// logit shift for free; clamp via min.f16x2 at 15.
// V plane 8 = ones => ssum accumulated exactly in fp32 by PV MMA.
// ============================================================
__global__ void __launch_bounds__(256) attn_hmma_kernel()
{
    __shared__ uint32_t sK[2][512];        // [buf][key*4 + dimpair]
    __shared__ uint32_t sV[2][16 * 68];    // [buf][plane*68 + keyword]
    int t = threadIdx.x, wid = t >> 5, lane = t & 31;
    int bid = blockIdx.x;
    int qt = bid % NQT;
    int nh = bid / NQT;
    int r = lane >> 2, cq = lane & 3;

    const uint32_t* kg = (const uint32_t*)g_kh + (size_t)nh * L * 4;
    const uint32_t* vg = (const uint32_t*)g_vh + (size_t)nh * 16 * (L / 2);

    // Q fragments (constant over chunks)
    int q0 = qt * 128 + wid * 16;
    const uint32_t* qgp = (const uint32_t*)g_qh + (size_t)(nh * L + q0) * 4;
    uint32_t qa0 = qgp[r * 4 + cq];
    uint32_t qa1 = qgp[(r + 8) * 4 + cq];
    const uint32_t C15 = 0x4B804B80u;   // (15.0, 15.0) f16x2

    int pl = t >> 4, qw = t & 15;

    // preload chunk 0
    uint2 kreg = ((const uint2*)kg)[t];
    uint4 vreg = *(const uint4*)(vg + (size_t)pl * (L / 2) + qw * 4);
    ((uint2*)sK[0])[t] = kreg;
    *(uint4*)&sV[0][pl * 68 + qw * 4] = vreg;
    __syncthreads();

    float o0[4] = {0.f, 0.f, 0.f, 0.f};
    float o1[4] = {0.f, 0.f, 0.f, 0.f};

    for (int c = 0; c < NCHUNK; c++) {
        int cur = c & 1;
        if (c + 1 < NCHUNK) {   // register-staged prefetch
            kreg = ((const uint2*)(kg + (size_t)(c + 1) * 512))[t];
            vreg = *(const uint4*)(vg + (size_t)pl * (L / 2) + (c + 1) * 64 + qw * 4);
        }

        uint32_t pa[16], pb[16];
#pragma unroll
        for (int j = 0; j < 16; j++) {
            uint32_t kb = sK[cur][j * 32 + r * 4 + cq];
            // S - 9 via accumulator init (shift keeps e^S in f16 range)
            float s0 = -9.f, s1 = -9.f, s2 = -9.f, s3 = -9.f;
            HMMA8(s0, s1, s2, s3, qa0, qa1, kb);
            uint32_t x, y;
            asm("cvt.rn.f16x2.f32 %0, %1, %2;" : "=r"(x) : "f"(s1), "f"(s0));
            asm("min.f16x2 %0, %0, %1;" : "+r"(x) : "r"(C15));
            asm("ex2.approx.f16x2 %0, %1;" : "=r"(x) : "r"(x));
            asm("cvt.rn.f16x2.f32 %0, %1, %2;" : "=r"(y) : "f"(s3), "f"(s2));
            asm("min.f16x2 %0, %0, %1;" : "+r"(y) : "r"(C15));
            asm("ex2.approx.f16x2 %0, %1;" : "=r"(y) : "r"(y));
            pa[j] = x;
            pb[j] = y;
        }

#pragma unroll
        for (int s = 0; s < 8; s++) {
            uint32_t b0 = sV[cur][r * 68 + s * 8 + cq];
            uint32_t b1 = sV[cur][r * 68 + s * 8 + cq + 4];
            HMMA16(o0[0], o0[1], o0[2], o0[3],
                   pa[2 * s], pb[2 * s], pa[2 * s + 1], pb[2 * s + 1], b0, b1);
            uint32_t b2 = sV[cur][(r + 8) * 68 + s * 8 + cq];
            uint32_t b3 = sV[cur][(r + 8) * 68 + s * 8 + cq + 4];
            HMMA16(o1[0], o1[1], o1[2], o1[3],
                   pa[2 * s], pb[2 * s], pa[2 * s + 1], pb[2 * s + 1], b2, b3);
        }

        if (c + 1 < NCHUNK) {
            int nxt = cur ^ 1;
            ((uint2*)sK[nxt])[t] = kreg;
            *(uint4*)&sV[nxt][pl * 68 + qw * 4] = vreg;
        }
        __syncthreads();
    }

    // ssum lives in dim-8 column: o1[0]/o1[2] of lanes with cq==0
    float ss_lo = __shfl_sync(0xffffffffu, o1[0], lane & ~3);
    float ss_hi = __shfl_sync(0xffffffffu, o1[2], lane & ~3);
    float inv_lo = 1.f / fmaxf(ss_lo, 1e-30f);
    float inv_hi = 1.f / fmaxf(ss_hi, 1e-30f);

    int n = nh >> 3, h = nh & 7;
    float* dst = g_o + ((size_t)n * HCH + h * 8 + cq * 2) * L + q0 + r;
    dst[0]     = o0[0] * inv_lo;
    dst[8]     = o0[2] * inv_hi;
    dst[L]     = o0[1] * inv_lo;
    dst[L + 8] = o0[3] * inv_hi;
}

// ============================================================
// Pos 3x3 conv as implicit GEMM over V (round-3 measured-best form),
// K split across blockIdx.y for 2x occupancy; atomicAdd merge.
// grid (72, 2, 4) = 576 CTAs, 256 threads.
// ============================================================
__global__ void __launch_bounds__(256) pos_gemm_kernel(
    const float* __restrict__ pw, const float* __restrict__ pb)
{
    __shared__ float As[16][68];
    __shared__ float Bs[16][36];
    int n  = blockIdx.z;
    int ky = blockIdx.y;                 // K half: [ky*288, ky*288+288)
    int l0 = blockIdx.x * 32;
    int t  = threadIdx.x;
    int tm = t >> 4, tn = t & 15;

    float acc[4][2];
#pragma unroll
    for (int i = 0; i < 4; i++) { acc[i][0] = 0.f; acc[i][1] = 0.f; }

    int kbase = ky * 288;
    for (int k0 = kbase; k0 < kbase + 288; k0 += 16) {
        {   // A = pos weights [64 oc][576], transposed tile
            int m = t >> 2, kk = (t & 3) * 4;
            float4 a = *(const float4*)(pw + (size_t)m * 576 + k0 + kk);
            As[kk + 0][m] = a.x; As[kk + 1][m] = a.y;
            As[kk + 2][m] = a.z; As[kk + 3][m] = a.w;
        }
        {   // B = implicit im2col gather of V (2 elements per thread)
#pragma unroll
            for (int u = 0; u < 2; u++) {
                int e = t * 2 + u;
                int kk = e >> 5, col = e & 31;
                int k = k0 + kk;
                int ic = k / 9;
                int tap = k - ic * 9;
                int dy = tap / 3 - 1, dx = tap - (tap / 3) * 3 - 1;
                int px = l0 + col;
                int y = px / 48, x = px - y * 48;
                int gy = y + dy, gx = x + dx;
                float v = 0.f;
                if ((unsigned)gy < 48u && (unsigned)gx < 48u) {
                    int c = (ic >> 3) * 24 + 16 + (ic & 7);   // v channel in qkv
                    v = g_qkv[((size_t)n * 192 + c) * L + gy * 48 + gx];
                }
                Bs[kk][col] = v;
            }
        }
        __syncthreads();
#pragma unroll
        for (int kk = 0; kk < 16; kk++) {
            float4 a4 = *(const float4*)&As[kk][tm * 4];
            float2 b2 = *(const float2*)&Bs[kk][tn * 2];
            float ar[4] = {a4.x, a4.y, a4.z, a4.w};
#pragma unroll
            for (int i = 0; i < 4; i++) {
                acc[i][0] = fmaf(ar[i], b2.x, acc[i][0]);
                acc[i][1] = fmaf(ar[i], b2.y, acc[i][1]);
            }
        }
        __syncthreads();
    }

#pragma unroll
    for (int i = 0; i < 4; i++) {
        int m = tm * 4 + i;
        float bb = (ky == 0) ? pb[m] : 0.f;
        float* dst = g_o + ((size_t)n * HCH + m) * L + l0 + tn * 2;
        atomicAdd(dst,     acc[i][0] + bb);
        atomicAdd(dst + 1, acc[i][1] + bb);
    }
}

// ============================================================
extern "C" void kernel_launch(void* const* d_in, const int* in_sizes, int n_in,
                              void* d_out, int out_size)
{
    const float* x     = (const float*)d_in[0];
    const float* qkv_w = (const float*)d_in[1];
    const float* qkv_b = (const float*)d_in[2];
    const float* pos_w = (const float*)d_in[3];
    const float* pos_b = (const float*)d_in[4];
    const float* res_w = (const float*)d_in[5];
    const float* res_b = (const float*)d_in[6];
    float* out = (float*)d_out;

    float* qkv_ptr = nullptr;
    float* o_ptr   = nullptr;
    cudaGetSymbolAddress((void**)&qkv_ptr, g_qkv);
    cudaGetSymbolAddress((void**)&o_ptr, g_o);

    // K1: qkv 1x1 conv as GEMM
    gemm_bias_kernel<<<dim3(18, 3, NBATCH), 256>>>(qkv_w, x, qkv_b, qkv_ptr, 192, CIN);

    // K2: fp32 -> fp16 fragment images
    {
        int total = NT_Q + NT_K + NT_V;
        convert_kernel<<<(total + 255) / 256, 256>>>();
    }

    // K3: attention (HMMA tensor cores)
    attn_hmma_kernel<<<NNH * NQT, 256>>>();

    // K4: pos conv (K-split, atomicAdd into g_o)
    pos_gemm_kernel<<<dim3(72, 2, NBATCH), 256>>>(pos_w, pos_b);

    // K5: res 1x1 conv as GEMM
    gemm_bias_kernel<<<dim3(18, 8, NBATCH), 256>>>(res_w, o_ptr, res_b, out, 512, HCH);
}

// round 10
// speedup vs baseline: 1.3388x; 1.1050x over previous
#include <cuda_runtime.h>
#include <cuda_fp16.h>
#include <cstdint>

#define L 2304
#define NBATCH 4
#define CIN 512
#define HCH 64
#define NH 8
#define NNH (NBATCH * NH)        // 32
#define NQT 18                   // q tiles of 128
#define NCHUNK 18                // key chunks of 128
#define NCB 288                  // column blocks of 8 over L

// scratch (no cudaMalloc allowed)
__device__ float g_qkv[NBATCH * 192 * L];        // [n][192][L] fp32
__device__ float g_o[NBATCH * HCH * L];          // [n][64][L]
__device__ __half g_qh[NNH * L * 8];             // [nh][q][8]  (scaled)
__device__ __half g_kh[NNH * L * 8];             // [nh][k][8]
__device__ __half g_vh[NNH * 16 * L];            // [nh][dim16][k], plane8=ones
// split-f16 fragment images for the 1x1-conv GEMMs
__device__ uint4 g_qwf_h[12 * 32 * 32];          // qkv_w A-frags hi  [mb][kblk][lane]
__device__ uint4 g_qwf_l[12 * 32 * 32];
__device__ uint4 g_rwf_h[32 * 4 * 32];           // res_w A-frags
__device__ uint4 g_rwf_l[32 * 4 * 32];
__device__ uint2 g_xf_h[NBATCH * NCB * 32 * 32]; // x B-frags [nb][cb][kblk][lane]
__device__ uint2 g_xf_l[NBATCH * NCB * 32 * 32];
__device__ uint2 g_of_h[NBATCH * NCB * 4 * 32];  // attention-out B-frags
__device__ uint2 g_of_l[NBATCH * NCB * 4 * 32];

#define HMMA16(c0, c1, c2, c3, a0, a1, a2, a3, b0, b1) \
    asm volatile("mma.sync.aligned.m16n8k16.row.col.f32.f16.f16.f32 " \
        "{%0,%1,%2,%3}, {%4,%5,%6,%7}, {%8,%9}, {%0,%1,%2,%3};" \
        : "+f"(c0), "+f"(c1), "+f"(c2), "+f"(c3) \
        : "r"(a0), "r"(a1), "r"(a2), "r"(a3), "r"(b0), "r"(b1))

#define HMMA8(c0, c1, c2, c3, a0, a1, b0) \
    asm volatile("mma.sync.aligned.m16n8k8.row.col.f32.f16.f16.f32 " \
        "{%0,%1,%2,%3}, {%4,%5}, {%6}, {%0,%1,%2,%3};" \
        : "+f"(c0), "+f"(c1), "+f"(c2), "+f"(c3) \
        : "r"(a0), "r"(a1), "r"(b0))

// split a,b (fp32) into hi/lo f16 pairs packed as (low-k in low 16 bits)
__device__ __forceinline__ uint32_t split_pack(float a, float b, uint32_t& lo) {
    __half ha = __float2half_rn(a), hb = __float2half_rn(b);
    __half la = __float2half_rn(a - __half2float(ha));
    __half lb = __float2half_rn(b - __half2float(hb));
    lo = ((uint32_t)__half_as_ushort(lb) << 16) | __half_as_ushort(la);
    return ((uint32_t)__half_as_ushort(hb) << 16) | __half_as_ushort(ha);
}

// ============================================================
// A-fragment builder: src [M][K] fp32 row-major -> frag arrays
// [mb][kblk][lane] uint4 = (a0,a1,a2,a3) for mma.m16n8k16.
// ============================================================
__global__ void __launch_bounds__(256) afrag_split_kernel(
    const float* __restrict__ src, uint4* __restrict__ dh, uint4* __restrict__ dl,
    int K, int NKB, int total)
{
    int id = blockIdx.x * 256 + threadIdx.x;
    if (id >= total) return;
    int lane = id & 31;
    int kblk = (id >> 5) % NKB;
    int mb   = id / (32 * NKB);
    int row = mb * 16 + (lane >> 2);
    int w   = kblk * 8 + (lane & 3);
    const float* s0 = src + (size_t)row * K;
    const float* s1 = s0 + 8 * K;
    uint4 hi, lo;
    hi.x = split_pack(s0[2 * w],     s0[2 * w + 1], lo.x);
    hi.y = split_pack(s1[2 * w],     s1[2 * w + 1], lo.y);
    hi.z = split_pack(s0[2 * w + 8], s0[2 * w + 9], lo.z);
    hi.w = split_pack(s1[2 * w + 8], s1[2 * w + 9], lo.w);
    dh[id] = hi;
    dl[id] = lo;
}

// ============================================================
// B-fragment builder: src [nb][Kch][L] fp32 -> [nb][cb][kblk][lane]
// uint2 = (b0,b1) for mma.m16n8k16 (col = l, k = channel).
// ============================================================
__global__ void __launch_bounds__(256) bfrag_split_kernel(
    const float* __restrict__ src, uint2* __restrict__ dh, uint2* __restrict__ dl,
    int Kch, int NKB, int total)
{
    int id = blockIdx.x * 256 + threadIdx.x;
    if (id >= total) return;
    int lane = id & 31;
    int kblk = (id >> 5) % NKB;
    int cb   = (id / (32 * NKB)) % NCB;
    int nb   = id / (32 * NKB * NCB);
    int col = cb * 8 + (lane >> 2);
    int w   = kblk * 8 + (lane & 3);
    const float* s = src + (size_t)nb * Kch * L + col;
    uint2 hi, lo;
    hi.x = split_pack(s[(size_t)(2 * w) * L],     s[(size_t)(2 * w + 1) * L], lo.x);
    hi.y = split_pack(s[(size_t)(2 * w + 8) * L], s[(size_t)(2 * w + 9) * L], lo.y);
    dh[id] = hi;
    dl[id] = lo;
}

// ============================================================
// Split-f16 HMMA GEMM: C[nb][m][l] = sum_k A[m][k]*B[nb][k][l] + bias[m]
// computed as Ah*Bh + Ah*Bl + Al*Bh in f32 accum (fp32-equivalent).
// Fragment-order global layouts; no smem, no syncthreads.
// grid (18, M/32, 4), 256 threads = 8 warps (2 m16 x 4 n32).
// ============================================================
__global__ void __launch_bounds__(256) hgemm_split_kernel(
    const uint4* __restrict__ Ah, const uint4* __restrict__ Al,
    const uint2* __restrict__ Bh, const uint2* __restrict__ Bl,
    const float* __restrict__ bias, float* __restrict__ C,
    int M, int NKB)
{
    int t = threadIdx.x, wid = t >> 5, lane = t & 31;
    int mw = wid >> 2, nw = wid & 3;
    int mb  = blockIdx.y * 2 + mw;
    int cb0 = blockIdx.x * 16 + nw * 4;
    int nb  = blockIdx.z;
    int r = lane >> 2, cq = lane & 3;

    float a1c[4][4], a2c[4][4];
#pragma unroll
    for (int j = 0; j < 4; j++)
#pragma unroll
        for (int i = 0; i < 4; i++) { a1c[j][i] = 0.f; a2c[j][i] = 0.f; }

    const uint4* pah = Ah + (size_t)mb * NKB * 32 + lane;
    const uint4* pal = Al + (size_t)mb * NKB * 32 + lane;
    const uint2* pbh = Bh + ((size_t)nb * NCB + cb0) * NKB * 32 + lane;
    const uint2* pbl = Bl + ((size_t)nb * NCB + cb0) * NKB * 32 + lane;

#pragma unroll 4
    for (int kb = 0; kb < NKB; kb++) {
        uint4 ah = pah[kb * 32];
        uint4 al = pal[kb * 32];
#pragma unroll
        for (int j = 0; j < 4; j++) {
            uint2 bh = pbh[(j * NKB + kb) * 32];
            uint2 bl = pbl[(j * NKB + kb) * 32];
            HMMA16(a1c[j][0], a1c[j][1], a1c[j][2], a1c[j][3],
                   ah.x, ah.y, ah.z, ah.w, bh.x, bh.y);
            HMMA16(a2c[j][0], a2c[j][1], a2c[j][2], a2c[j][3],
                   ah.x, ah.y, ah.z, ah.w, bl.x, bl.y);
            HMMA16(a2c[j][0], a2c[j][1], a2c[j][2], a2c[j][3],
                   al.x, al.y, al.z, al.w, bh.x, bh.y);
        }
    }

    int row0 = mb * 16 + r;
    float b0 = bias[row0], b1 = bias[row0 + 8];
    float* base0 = C + ((size_t)nb * M + row0) * L;
    float* base1 = base0 + 8 * L;
#pragma unroll
    for (int j = 0; j < 4; j++) {
        int col = (cb0 + j) * 8 + cq * 2;
        float2 r0 = make_float2(a1c[j][0] + a2c[j][0] + b0,
                                a1c[j][1] + a2c[j][1] + b0);
        float2 r1 = make_float2(a1c[j][2] + a2c[j][2] + b1,
                                a1c[j][3] + a2c[j][3] + b1);
        *(float2*)(base0 + col) = r0;
        *(float2*)(base1 + col) = r1;
    }
}

// ============================================================
// Convert fp32 qkv -> fp16 fragment-friendly images (attention).
// ============================================================
#define NT_Q (NNH * L)
#define NT_K (NNH * L)
#define NT_V (NNH * 16 * (L / 8))

__global__ void __launch_bounds__(256) convert_kernel()
{
    const float QS = 0.35355339059327373f * 1.4426950408889634f;
    int id = blockIdx.x * 256 + threadIdx.x;

    if (id < NT_Q) {
        int nh = id / L, q = id - nh * L;
        int n = nh >> 3, h = nh & 7;
        const float* src = g_qkv + ((size_t)n * 192 + h * 24) * L + q;
        uint32_t w[4];
#pragma unroll
        for (int j = 0; j < 4; j++) {
            __half2 h2 = __floats2half2_rn(src[(size_t)(2 * j) * L] * QS,
                                           src[(size_t)(2 * j + 1) * L] * QS);
            w[j] = *(uint32_t*)&h2;
        }
        ((uint4*)g_qh)[id] = make_uint4(w[0], w[1], w[2], w[3]);
        return;
    }
    id -= NT_Q;
    if (id < NT_K) {
        int nh = id / L, k = id - nh * L;
        int n = nh >> 3, h = nh & 7;
        const float* src = g_qkv + ((size_t)n * 192 + h * 24 + 8) * L + k;
        uint32_t w[4];
#pragma unroll
        for (int j = 0; j < 4; j++) {
            __half2 h2 = __floats2half2_rn(src[(size_t)(2 * j) * L],
                                           src[(size_t)(2 * j + 1) * L]);
            w[j] = *(uint32_t*)&h2;
        }
        ((uint4*)g_kh)[id] = make_uint4(w[0], w[1], w[2], w[3]);
        return;
    }
    id -= NT_K;
    if (id < NT_V) {
        int nh = id / (16 * (L / 8));
        int rem = id - nh * 16 * (L / 8);
        int dim = rem / (L / 8);
        int blk = rem - dim * (L / 8);
        uint4 out;
        if (dim < 8) {
            int n = nh >> 3, h = nh & 7;
            const float* src = g_qkv + ((size_t)n * 192 + h * 24 + 16 + dim) * L + blk * 8;
            float4 f0 = *(const float4*)src;
            float4 f1 = *(const float4*)(src + 4);
            __half2 a = __floats2half2_rn(f0.x, f0.y);
            __half2 b = __floats2half2_rn(f0.z, f0.w);
            __half2 c = __floats2half2_rn(f1.x, f1.y);
            __half2 d = __floats2half2_rn(f1.z, f1.w);
            out = make_uint4(*(uint32_t*)&a, *(uint32_t*)&b, *(uint32_t*)&c, *(uint32_t*)&d);
        } else if (dim == 8) {
            out = make_uint4(0x3C003C00u, 0x3C003C00u, 0x3C003C00u, 0x3C003C00u);
        } else {
            out = make_uint4(0, 0, 0, 0);
        }
        ((uint4*)g_vh)[(size_t)(nh * 16 + dim) * (L / 8) + blk] = out;
    }
}

// ============================================================
// Attention via HMMA (f16 in, f32 accum).
// ============================================================
__global__ void __launch_bounds__(256) attn_hmma_kernel()
{
    __shared__ uint32_t sK[2][512];
    __shared__ uint32_t sV[2][16 * 68];
    int t = threadIdx.x, wid = t >> 5, lane = t & 31;
    int bid = blockIdx.x;
    int qt = bid % NQT;
    int nh = bid / NQT;
    int r = lane >> 2, cq = lane & 3;

    const uint32_t* kg = (const uint32_t*)g_kh + (size_t)nh * L * 4;
    const uint32_t* vg = (const uint32_t*)g_vh + (size_t)nh * 16 * (L / 2);

    int q0 = qt * 128 + wid * 16;
    const uint32_t* qgp = (const uint32_t*)g_qh + (size_t)(nh * L + q0) * 4;
    uint32_t qa0 = qgp[r * 4 + cq];
    uint32_t qa1 = qgp[(r + 8) * 4 + cq];
    const uint32_t C15 = 0x4B804B80u;

    int pl = t >> 4, qw = t & 15;

    uint2 kreg = ((const uint2*)kg)[t];
    uint4 vreg = *(const uint4*)(vg + (size_t)pl * (L / 2) + qw * 4);
    ((uint2*)sK[0])[t] = kreg;
    *(uint4*)&sV[0][pl * 68 + qw * 4] = vreg;
    __syncthreads();

    float o0[4] = {0.f, 0.f, 0.f, 0.f};
    float o1[4] = {0.f, 0.f, 0.f, 0.f};

    for (int c = 0; c < NCHUNK; c++) {
        int cur = c & 1;
        if (c + 1 < NCHUNK) {
            kreg = ((const uint2*)(kg + (size_t)(c + 1) * 512))[t];
            vreg = *(const uint4*)(vg + (size_t)pl * (L / 2) + (c + 1) * 64 + qw * 4);
        }

        uint32_t pa[16], pb[16];
#pragma unroll
        for (int j = 0; j < 16; j++) {
            uint32_t kb = sK[cur][j * 32 + r * 4 + cq];
            float s0 = -9.f, s1 = -9.f, s2 = -9.f, s3 = -9.f;
            HMMA8(s0, s1, s2, s3, qa0, qa1, kb);
            uint32_t x, y;
            asm("cvt.rn.f16x2.f32 %0, %1, %2;" : "=r"(x) : "f"(s1), "f"(s0));
            asm("min.f16x2 %0, %0, %1;" : "+r"(x) : "r"(C15));
            asm("ex2.approx.f16x2 %0, %1;" : "=r"(x) : "r"(x));
            asm("cvt.rn.f16x2.f32 %0, %1, %2;" : "=r"(y) : "f"(s3), "f"(s2));
            asm("min.f16x2 %0, %0, %1;" : "+r"(y) : "r"(C15));
            asm("ex2.approx.f16x2 %0, %1;" : "=r"(y) : "r"(y));
            pa[j] = x;
            pb[j] = y;
        }

#pragma unroll
        for (int s = 0; s < 8; s++) {
            uint32_t b0 = sV[cur][r * 68 + s * 8 + cq];
            uint32_t b1 = sV[cur][r * 68 + s * 8 + cq + 4];
            HMMA16(o0[0], o0[1], o0[2], o0[3],
                   pa[2 * s], pb[2 * s], pa[2 * s + 1], pb[2 * s + 1], b0, b1);
            uint32_t b2 = sV[cur][(r + 8) * 68 + s * 8 + cq];
            uint32_t b3 = sV[cur][(r + 8) * 68 + s * 8 + cq + 4];
            HMMA16(o1[0], o1[1], o1[2], o1[3],
                   pa[2 * s], pb[2 * s], pa[2 * s + 1], pb[2 * s + 1], b2, b3);
        }

        if (c + 1 < NCHUNK) {
            int nxt = cur ^ 1;
            ((uint2*)sK[nxt])[t] = kreg;
            *(uint4*)&sV[nxt][pl * 68 + qw * 4] = vreg;
        }
        __syncthreads();
    }

    float ss_lo = __shfl_sync(0xffffffffu, o1[0], lane & ~3);
    float ss_hi = __shfl_sync(0xffffffffu, o1[2], lane & ~3);
    float inv_lo = 1.f / fmaxf(ss_lo, 1e-30f);
    float inv_hi = 1.f / fmaxf(ss_hi, 1e-30f);

    int n = nh >> 3, h = nh & 7;
    float* dst = g_o + ((size_t)n * HCH + h * 8 + cq * 2) * L + q0 + r;
    dst[0]     = o0[0] * inv_lo;
    dst[8]     = o0[2] * inv_hi;
    dst[L]     = o0[1] * inv_lo;
    dst[L + 8] = o0[3] * inv_hi;
}

// ============================================================
// Pos 3x3 conv as implicit GEMM over V, K-split 2x, atomicAdd merge.
// grid (72, 2, 4) = 576 CTAs.
// ============================================================
__global__ void __launch_bounds__(256) pos_gemm_kernel(
    const float* __restrict__ pw, const float* __restrict__ pb)
{
    __shared__ float As[16][68];
    __shared__ float Bs[16][36];
    int n  = blockIdx.z;
    int ky = blockIdx.y;
    int l0 = blockIdx.x * 32;
    int t  = threadIdx.x;
    int tm = t >> 4, tn = t & 15;

    float acc[4][2];
#pragma unroll
    for (int i = 0; i < 4; i++) { acc[i][0] = 0.f; acc[i][1] = 0.f; }

    int kbase = ky * 288;
    for (int k0 = kbase; k0 < kbase + 288; k0 += 16) {
        {
            int m = t >> 2, kk = (t & 3) * 4;
            float4 a = *(const float4*)(pw + (size_t)m * 576 + k0 + kk);
            As[kk + 0][m] = a.x; As[kk + 1][m] = a.y;
            As[kk + 2][m] = a.z; As[kk + 3][m] = a.w;
        }
        {
#pragma unroll
            for (int u = 0; u < 2; u++) {
                int e = t * 2 + u;
                int kk = e >> 5, col = e & 31;
                int k = k0 + kk;
                int ic = k / 9;
                int tap = k - ic * 9;
                int dy = tap / 3 - 1, dx = tap - (tap / 3) * 3 - 1;
                int px = l0 + col;
                int y = px / 48, x = px - y * 48;
                int gy = y + dy, gx = x + dx;
                float v = 0.f;
                if ((unsigned)gy < 48u && (unsigned)gx < 48u) {
                    int c = (ic >> 3) * 24 + 16 + (ic & 7);
                    v = g_qkv[((size_t)n * 192 + c) * L + gy * 48 + gx];
                }
                Bs[kk][col] = v;
            }
        }
        __syncthreads();
#pragma unroll
        for (int kk = 0; kk < 16; kk++) {
            float4 a4 = *(const float4*)&As[kk][tm * 4];
            float2 b2 = *(const float2*)&Bs[kk][tn * 2];
            float ar[4] = {a4.x, a4.y, a4.z, a4.w};
#pragma unroll
            for (int i = 0; i < 4; i++) {
                acc[i][0] = fmaf(ar[i], b2.x, acc[i][0]);
                acc[i][1] = fmaf(ar[i], b2.y, acc[i][1]);
            }
        }
        __syncthreads();
    }

#pragma unroll
    for (int i = 0; i < 4; i++) {
        int m = tm * 4 + i;
        float bb = (ky == 0) ? pb[m] : 0.f;
        float* dst = g_o + ((size_t)n * HCH + m) * L + l0 + tn * 2;
        atomicAdd(dst,     acc[i][0] + bb);
        atomicAdd(dst + 1, acc[i][1] + bb);
    }
}

// ============================================================
extern "C" void kernel_launch(void* const* d_in, const int* in_sizes, int n_in,
                              void* d_out, int out_size)
{
    const float* x     = (const float*)d_in[0];
    const float* qkv_w = (const float*)d_in[1];
    const float* qkv_b = (const float*)d_in[2];
    const float* pos_w = (const float*)d_in[3];
    const float* pos_b = (const float*)d_in[4];
    const float* res_w = (const float*)d_in[5];
    const float* res_b = (const float*)d_in[6];
    float* out = (float*)d_out;

    float* qkv_ptr = nullptr;
    float* o_ptr   = nullptr;
    cudaGetSymbolAddress((void**)&qkv_ptr, g_qkv);
    cudaGetSymbolAddress((void**)&o_ptr, g_o);
    uint4 *qwf_h, *qwf_l, *rwf_h, *rwf_l;
    uint2 *xf_h, *xf_l, *of_h, *of_l;
    cudaGetSymbolAddress((void**)&qwf_h, g_qwf_h);
    cudaGetSymbolAddress((void**)&qwf_l, g_qwf_l);
    cudaGetSymbolAddress((void**)&rwf_h, g_rwf_h);
    cudaGetSymbolAddress((void**)&rwf_l, g_rwf_l);
    cudaGetSymbolAddress((void**)&xf_h, g_xf_h);
    cudaGetSymbolAddress((void**)&xf_l, g_xf_l);
    cudaGetSymbolAddress((void**)&of_h, g_of_h);
    cudaGetSymbolAddress((void**)&of_l, g_of_l);

    // K1a: build A-frags for qkv_w [192x512] and res_w [512x64]
    afrag_split_kernel<<<48, 256>>>(qkv_w, qwf_h, qwf_l, 512, 32, 12 * 32 * 32);
    afrag_split_kernel<<<16, 256>>>(res_w, rwf_h, rwf_l, 64, 4, 32 * 4 * 32);
    // K1b: build B-frags for x
    {
        int total = NBATCH * NCB * 32 * 32;
        bfrag_split_kernel<<<(total + 255) / 256, 256>>>(x, xf_h, xf_l, 512, 32, total);
    }
    // K1c: qkv GEMM (split-f16 HMMA) -> g_qkv
    hgemm_split_kernel<<<dim3(18, 6, NBATCH), 256>>>(
        qwf_h, qwf_l, xf_h, xf_l, qkv_b, qkv_ptr, 192, 32);

    // K2: attention fragment images
    {
        int total = NT_Q + NT_K + NT_V;
        convert_kernel<<<(total + 255) / 256, 256>>>();
    }

    // K3: attention (HMMA tensor cores)
    attn_hmma_kernel<<<NNH * NQT, 256>>>();

    // K4: pos conv (K-split, atomicAdd into g_o)
    pos_gemm_kernel<<<dim3(72, 2, NBATCH), 256>>>(pos_w, pos_b);

    // K5a: build B-frags for attention+pos output
    {
        int total = NBATCH * NCB * 4 * 32;
        bfrag_split_kernel<<<(total + 255) / 256, 256>>>(o_ptr, of_h, of_l, 64, 4, total);
    }
    // K5b: res GEMM (split-f16 HMMA) -> out
    hgemm_split_kernel<<<dim3(18, 16, NBATCH), 256>>>(
        rwf_h, rwf_l, of_h, of_l, res_b, out, 512, 4);
}

// round 11
// speedup vs baseline: 1.4739x; 1.1009x over previous
#include <cuda_runtime.h>
#include <cuda_fp16.h>
#include <cstdint>

#define L 2304
#define NBATCH 4
#define CIN 512
#define HCH 64
#define NH 8
#define NNH (NBATCH * NH)        // 32
#define NQT 18                   // q tiles of 128
#define NCHUNK 18                // key chunks of 128
#define NCB 288                  // column blocks of 8 over L

// scratch (no cudaMalloc allowed)
__device__ float g_qkv[NBATCH * 192 * L];        // [n][192][L] fp32
__device__ float g_o[NBATCH * HCH * L];          // [n][64][L]
__device__ __half g_qh[NNH * L * 8];             // [nh][q][8]  (scaled)
__device__ __half g_kh[NNH * L * 8];             // [nh][k][8]
__device__ __half g_vh[NNH * 16 * L];            // [nh][dim16][k], plane8=ones
// split-f16 fragment images (hi/lo interleaved)
__device__ uint4 g_qwf[12 * 32 * 32 * 2];        // qkv_w A-frags {hi,lo}
__device__ uint4 g_rwf[32 * 4 * 32 * 2];         // res_w A-frags
__device__ uint4 g_xf[NBATCH * NCB * 32 * 32];   // x B-frags {bh0,bh1,bl0,bl1}
__device__ uint4 g_of[NBATCH * NCB * 4 * 32];    // attn-out B-frags

#define HMMA16(c0, c1, c2, c3, a0, a1, a2, a3, b0, b1) \
    asm volatile("mma.sync.aligned.m16n8k16.row.col.f32.f16.f16.f32 " \
        "{%0,%1,%2,%3}, {%4,%5,%6,%7}, {%8,%9}, {%0,%1,%2,%3};" \
        : "+f"(c0), "+f"(c1), "+f"(c2), "+f"(c3) \
        : "r"(a0), "r"(a1), "r"(a2), "r"(a3), "r"(b0), "r"(b1))

#define HMMA8(c0, c1, c2, c3, a0, a1, b0) \
    asm volatile("mma.sync.aligned.m16n8k8.row.col.f32.f16.f16.f32 " \
        "{%0,%1,%2,%3}, {%4,%5}, {%6}, {%0,%1,%2,%3};" \
        : "+f"(c0), "+f"(c1), "+f"(c2), "+f"(c3) \
        : "r"(a0), "r"(a1), "r"(b0))

__device__ __forceinline__ uint32_t split_pack(float a, float b, uint32_t& lo) {
    __half ha = __float2half_rn(a), hb = __float2half_rn(b);
    __half la = __float2half_rn(a - __half2float(ha));
    __half lb = __float2half_rn(b - __half2float(hb));
    lo = ((uint32_t)__half_as_ushort(lb) << 16) | __half_as_ushort(la);
    return ((uint32_t)__half_as_ushort(hb) << 16) | __half_as_ushort(ha);
}

// ============================================================
// A-fragment builder: src [M][K] fp32 -> {hi,lo} uint4 pairs.
// ============================================================
__global__ void __launch_bounds__(256) afrag_split_kernel(
    const float* __restrict__ src, uint4* __restrict__ dst,
    int K, int NKB, int total)
{
    int id = blockIdx.x * 256 + threadIdx.x;
    if (id >= total) return;
    int lane = id & 31;
    int kblk = (id >> 5) % NKB;
    int mb   = id / (32 * NKB);
    int row = mb * 16 + (lane >> 2);
    int w   = kblk * 8 + (lane & 3);
    const float* s0 = src + (size_t)row * K;
    const float* s1 = s0 + 8 * K;
    uint4 hi, lo;
    hi.x = split_pack(s0[2 * w],     s0[2 * w + 1], lo.x);
    hi.y = split_pack(s1[2 * w],     s1[2 * w + 1], lo.y);
    hi.z = split_pack(s0[2 * w + 8], s0[2 * w + 9], lo.z);
    hi.w = split_pack(s1[2 * w + 8], s1[2 * w + 9], lo.w);
    dst[id * 2]     = hi;
    dst[id * 2 + 1] = lo;
}

// ============================================================
// B-fragment builder: src [nb][Kch][L] -> uint4 {bh0,bh1,bl0,bl1}.
// ============================================================
__global__ void __launch_bounds__(256) bfrag_split_kernel(
    const float* __restrict__ src, uint4* __restrict__ dst,
    int Kch, int NKB, int total)
{
    int id = blockIdx.x * 256 + threadIdx.x;
    if (id >= total) return;
    int lane = id & 31;
    int kblk = (id >> 5) % NKB;
    int cb   = (id / (32 * NKB)) % NCB;
    int nb   = id / (32 * NKB * NCB);
    int col = cb * 8 + (lane >> 2);
    int w   = kblk * 8 + (lane & 3);
    const float* s = src + (size_t)nb * Kch * L + col;
    uint4 o;
    o.x = split_pack(s[(size_t)(2 * w) * L],     s[(size_t)(2 * w + 1) * L], o.z);
    o.y = split_pack(s[(size_t)(2 * w + 8) * L], s[(size_t)(2 * w + 9) * L], o.w);
    dst[id] = o;
}

// ============================================================
// Split-f16 HMMA GEMM, register-prefetched, optional K-split.
// C[nb][m][l] = sum_k A[m][k]*B[nb][k][l] (+bias).
// addmode=1: atomicAdd into zeroed C, bias applied by ky==0.
// grid (18, MBT*ksplit, NBATCH), 256 thr = 8 warps (2 m16 x 4 cb4).
// ============================================================
__global__ void __launch_bounds__(256) hgemm_split_kernel(
    const uint4* __restrict__ Af, const uint4* __restrict__ Bf,
    const float* __restrict__ bias, float* __restrict__ C,
    int M, int NKB, int ksplit, int addmode)
{
    int t = threadIdx.x, wid = t >> 5, lane = t & 31;
    int mw = wid >> 2, nw = wid & 3;
    int mbt = blockIdx.y / ksplit;
    int ky  = blockIdx.y % ksplit;
    int mb  = mbt * 2 + mw;
    int cb0 = blockIdx.x * 16 + nw * 4;
    int nb  = blockIdx.z;
    int r = lane >> 2, cq = lane & 3;
    int kbN = NKB / ksplit;
    int kb0 = ky * kbN;

    const uint4* pa = Af + ((size_t)mb * NKB + kb0) * 64 + lane * 2;
    const uint4* pb = Bf + (((size_t)nb * NCB + cb0) * NKB + kb0) * 32 + lane;

    float a1c[4][4], a2c[4][4];
#pragma unroll
    for (int j = 0; j < 4; j++)
#pragma unroll
        for (int i = 0; i < 4; i++) { a1c[j][i] = 0.f; a2c[j][i] = 0.f; }

    uint4 nB[4];
#pragma unroll
    for (int j = 0; j < 4; j++) nB[j] = pb[(size_t)j * NKB * 32];

    for (int kb = 0; kb < kbN; kb++) {
        uint4 cB[4];
#pragma unroll
        for (int j = 0; j < 4; j++) cB[j] = nB[j];
        if (kb + 1 < kbN) {
#pragma unroll
            for (int j = 0; j < 4; j++)
                nB[j] = pb[((size_t)j * NKB + kb + 1) * 32];
        }
        uint4 ah = pa[kb * 64];
        uint4 al = pa[kb * 64 + 1];
#pragma unroll
        for (int j = 0; j < 4; j++) {
            HMMA16(a1c[j][0], a1c[j][1], a1c[j][2], a1c[j][3],
                   ah.x, ah.y, ah.z, ah.w, cB[j].x, cB[j].y);
            HMMA16(a2c[j][0], a2c[j][1], a2c[j][2], a2c[j][3],
                   ah.x, ah.y, ah.z, ah.w, cB[j].z, cB[j].w);
            HMMA16(a2c[j][0], a2c[j][1], a2c[j][2], a2c[j][3],
                   al.x, al.y, al.z, al.w, cB[j].x, cB[j].y);
        }
    }

    int row0 = mb * 16 + r;
    float b0 = 0.f, b1 = 0.f;
    if (!addmode || ky == 0) { b0 = bias[row0]; b1 = bias[row0 + 8]; }
    float* base0 = C + ((size_t)nb * M + row0) * L;
    float* base1 = base0 + 8 * L;
#pragma unroll
    for (int j = 0; j < 4; j++) {
        int col = (cb0 + j) * 8 + cq * 2;
        float v00 = a1c[j][0] + a2c[j][0] + b0;
        float v01 = a1c[j][1] + a2c[j][1] + b0;
        float v10 = a1c[j][2] + a2c[j][2] + b1;
        float v11 = a1c[j][3] + a2c[j][3] + b1;
        if (addmode) {
            atomicAdd(base0 + col,     v00);
            atomicAdd(base0 + col + 1, v01);
            atomicAdd(base1 + col,     v10);
            atomicAdd(base1 + col + 1, v11);
        } else {
            *(float2*)(base0 + col) = make_float2(v00, v01);
            *(float2*)(base1 + col) = make_float2(v10, v11);
        }
    }
}

// ============================================================
// Convert fp32 qkv -> fp16 fragment-friendly images (attention).
// ============================================================
#define NT_Q (NNH * L)
#define NT_K (NNH * L)
#define NT_V (NNH * 16 * (L / 8))

__global__ void __launch_bounds__(256) convert_kernel()
{
    const float QS = 0.35355339059327373f * 1.4426950408889634f;
    int id = blockIdx.x * 256 + threadIdx.x;

    if (id < NT_Q) {
        int nh = id / L, q = id - nh * L;
        int n = nh >> 3, h = nh & 7;
        const float* src = g_qkv + ((size_t)n * 192 + h * 24) * L + q;
        uint32_t w[4];
#pragma unroll
        for (int j = 0; j < 4; j++) {
            __half2 h2 = __floats2half2_rn(src[(size_t)(2 * j) * L] * QS,
                                           src[(size_t)(2 * j + 1) * L] * QS);
            w[j] = *(uint32_t*)&h2;
        }
        ((uint4*)g_qh)[id] = make_uint4(w[0], w[1], w[2], w[3]);
        return;
    }
    id -= NT_Q;
    if (id < NT_K) {
        int nh = id / L, k = id - nh * L;
        int n = nh >> 3, h = nh & 7;
        const float* src = g_qkv + ((size_t)n * 192 + h * 24 + 8) * L + k;
        uint32_t w[4];
#pragma unroll
        for (int j = 0; j < 4; j++) {
            __half2 h2 = __floats2half2_rn(src[(size_t)(2 * j) * L],
                                           src[(size_t)(2 * j + 1) * L]);
            w[j] = *(uint32_t*)&h2;
        }
        ((uint4*)g_kh)[id] = make_uint4(w[0], w[1], w[2], w[3]);
        return;
    }
    id -= NT_K;
    if (id < NT_V) {
        int nh = id / (16 * (L / 8));
        int rem = id - nh * 16 * (L / 8);
        int dim = rem / (L / 8);
        int blk = rem - dim * (L / 8);
        uint4 out;
        if (dim < 8) {
            int n = nh >> 3, h = nh & 7;
            const float* src = g_qkv + ((size_t)n * 192 + h * 24 + 16 + dim) * L + blk * 8;
            float4 f0 = *(const float4*)src;
            float4 f1 = *(const float4*)(src + 4);
            __half2 a = __floats2half2_rn(f0.x, f0.y);
            __half2 b = __floats2half2_rn(f0.z, f0.w);
            __half2 c = __floats2half2_rn(f1.x, f1.y);
            __half2 d = __floats2half2_rn(f1.z, f1.w);
            out = make_uint4(*(uint32_t*)&a, *(uint32_t*)&b, *(uint32_t*)&c, *(uint32_t*)&d);
        } else if (dim == 8) {
            out = make_uint4(0x3C003C00u, 0x3C003C00u, 0x3C003C00u, 0x3C003C00u);
        } else {
            out = make_uint4(0, 0, 0, 0);
        }
        ((uint4*)g_vh)[(size_t)(nh * 16 + dim) * (L / 8) + blk] = out;
    }
}

// ============================================================
// Attention via HMMA (f16 in, f32 accum).
// ============================================================
__global__ void __launch_bounds__(256) attn_hmma_kernel()
{
    __shared__ uint32_t sK[2][512];
    __shared__ uint32_t sV[2][16 * 68];
    int t = threadIdx.x, wid = t >> 5, lane = t & 31;
    int bid = blockIdx.x;
    int qt = bid % NQT;
    int nh = bid / NQT;
    int r = lane >> 2, cq = lane & 3;

    const uint32_t* kg = (const uint32_t*)g_kh + (size_t)nh * L * 4;
    const uint32_t* vg = (const uint32_t*)g_vh + (size_t)nh * 16 * (L / 2);

    int q0 = qt * 128 + wid * 16;
    const uint32_t* qgp = (const uint32_t*)g_qh + (size_t)(nh * L + q0) * 4;
    uint32_t qa0 = qgp[r * 4 + cq];
    uint32_t qa1 = qgp[(r + 8) * 4 + cq];
    const uint32_t C15 = 0x4B804B80u;

    int pl = t >> 4, qw = t & 15;

    uint2 kreg = ((const uint2*)kg)[t];
    uint4 vreg = *(const uint4*)(vg + (size_t)pl * (L / 2) + qw * 4);
    ((uint2*)sK[0])[t] = kreg;
    *(uint4*)&sV[0][pl * 68 + qw * 4] = vreg;
    __syncthreads();

    float o0[4] = {0.f, 0.f, 0.f, 0.f};
    float o1[4] = {0.f, 0.f, 0.f, 0.f};

    for (int c = 0; c < NCHUNK; c++) {
        int cur = c & 1;
        if (c + 1 < NCHUNK) {
            kreg = ((const uint2*)(kg + (size_t)(c + 1) * 512))[t];
            vreg = *(const uint4*)(vg + (size_t)pl * (L / 2) + (c + 1) * 64 + qw * 4);
        }

        uint32_t pa[16], pb[16];
#pragma unroll
        for (int j = 0; j < 16; j++) {
            uint32_t kb = sK[cur][j * 32 + r * 4 + cq];
            float s0 = -9.f, s1 = -9.f, s2 = -9.f, s3 = -9.f;
            HMMA8(s0, s1, s2, s3, qa0, qa1, kb);
            uint32_t x, y;
            asm("cvt.rn.f16x2.f32 %0, %1, %2;" : "=r"(x) : "f"(s1), "f"(s0));
            asm("min.f16x2 %0, %0, %1;" : "+r"(x) : "r"(C15));
            asm("ex2.approx.f16x2 %0, %1;" : "=r"(x) : "r"(x));
            asm("cvt.rn.f16x2.f32 %0, %1, %2;" : "=r"(y) : "f"(s3), "f"(s2));
            asm("min.f16x2 %0, %0, %1;" : "+r"(y) : "r"(C15));
            asm("ex2.approx.f16x2 %0, %1;" : "=r"(y) : "r"(y));
            pa[j] = x;
            pb[j] = y;
        }

#pragma unroll
        for (int s = 0; s < 8; s++) {
            uint32_t b0 = sV[cur][r * 68 + s * 8 + cq];
            uint32_t b1 = sV[cur][r * 68 + s * 8 + cq + 4];
            HMMA16(o0[0], o0[1], o0[2], o0[3],
                   pa[2 * s], pb[2 * s], pa[2 * s + 1], pb[2 * s + 1], b0, b1);
            uint32_t b2 = sV[cur][(r + 8) * 68 + s * 8 + cq];
            uint32_t b3 = sV[cur][(r + 8) * 68 + s * 8 + cq + 4];
            HMMA16(o1[0], o1[1], o1[2], o1[3],
                   pa[2 * s], pb[2 * s], pa[2 * s + 1], pb[2 * s + 1], b2, b3);
        }

        if (c + 1 < NCHUNK) {
            int nxt = cur ^ 1;
            ((uint2*)sK[nxt])[t] = kreg;
            *(uint4*)&sV[nxt][pl * 68 + qw * 4] = vreg;
        }
        __syncthreads();
    }

    float ss_lo = __shfl_sync(0xffffffffu, o1[0], lane & ~3);
    float ss_hi = __shfl_sync(0xffffffffu, o1[2], lane & ~3);
    float inv_lo = 1.f / fmaxf(ss_lo, 1e-30f);
    float inv_hi = 1.f / fmaxf(ss_hi, 1e-30f);

    int n = nh >> 3, h = nh & 7;
    float* dst = g_o + ((size_t)n * HCH + h * 8 + cq * 2) * L + q0 + r;
    dst[0]     = o0[0] * inv_lo;
    dst[8]     = o0[2] * inv_hi;
    dst[L]     = o0[1] * inv_lo;
    dst[L + 8] = o0[3] * inv_hi;
}

// ============================================================
// Pos 3x3 conv as implicit GEMM over V, K-split 4x, atomicAdd merge.
// grid (72, 4, 4) = 1152 CTAs.
// ============================================================
__global__ void __launch_bounds__(256) pos_gemm_kernel(
    const float* __restrict__ pw, const float* __restrict__ pb)
{
    __shared__ float As[16][68];
    __shared__ float Bs[16][36];
    int n  = blockIdx.z;
    int ky = blockIdx.y;
    int l0 = blockIdx.x * 32;
    int t  = threadIdx.x;
    int tm = t >> 4, tn = t & 15;

    float acc[4][2];
#pragma unroll
    for (int i = 0; i < 4; i++) { acc[i][0] = 0.f; acc[i][1] = 0.f; }

    int kbase = ky * 144;
    for (int k0 = kbase; k0 < kbase + 144; k0 += 16) {
        {
            int m = t >> 2, kk = (t & 3) * 4;
            float4 a = *(const float4*)(pw + (size_t)m * 576 + k0 + kk);
            As[kk + 0][m] = a.x; As[kk + 1][m] = a.y;
            As[kk + 2][m] = a.z; As[kk + 3][m] = a.w;
        }
        {
#pragma unroll
            for (int u = 0; u < 2; u++) {
                int e = t * 2 + u;
                int kk = e >> 5, col = e & 31;
                int k = k0 + kk;
                int ic = k / 9;
                int tap = k - ic * 9;
                int dy = tap / 3 - 1, dx = tap - (tap / 3) * 3 - 1;
                int px = l0 + col;
                int y = px / 48, x = px - y * 48;
                int gy = y + dy, gx = x + dx;
                float v = 0.f;
                if ((unsigned)gy < 48u && (unsigned)gx < 48u) {
                    int c = (ic >> 3) * 24 + 16 + (ic & 7);
                    v = g_qkv[((size_t)n * 192 + c) * L + gy * 48 + gx];
                }
                Bs[kk][col] = v;
            }
        }
        __syncthreads();
#pragma unroll
        for (int kk = 0; kk < 16; kk++) {
            float4 a4 = *(const float4*)&As[kk][tm * 4];
            float2 b2 = *(const float2*)&Bs[kk][tn * 2];
            float ar[4] = {a4.x, a4.y, a4.z, a4.w};
#pragma unroll
            for (int i = 0; i < 4; i++) {
                acc[i][0] = fmaf(ar[i], b2.x, acc[i][0]);
                acc[i][1] = fmaf(ar[i], b2.y, acc[i][1]);
            }
        }
        __syncthreads();
    }

#pragma unroll
    for (int i = 0; i < 4; i++) {
        int m = tm * 4 + i;
        float bb = (ky == 0) ? pb[m] : 0.f;
        float* dst = g_o + ((size_t)n * HCH + m) * L + l0 + tn * 2;
        atomicAdd(dst,     acc[i][0] + bb);
        atomicAdd(dst + 1, acc[i][1] + bb);
    }
}

// ============================================================
extern "C" void kernel_launch(void* const* d_in, const int* in_sizes, int n_in,
                              void* d_out, int out_size)
{
    const float* x     = (const float*)d_in[0];
    const float* qkv_w = (const float*)d_in[1];
    const float* qkv_b = (const float*)d_in[2];
    const float* pos_w = (const float*)d_in[3];
    const float* pos_b = (const float*)d_in[4];
    const float* res_w = (const float*)d_in[5];
    const float* res_b = (const float*)d_in[6];
    float* out = (float*)d_out;

    float* qkv_ptr = nullptr;
    float* o_ptr   = nullptr;
    cudaGetSymbolAddress((void**)&qkv_ptr, g_qkv);
    cudaGetSymbolAddress((void**)&o_ptr, g_o);
    uint4 *qwf, *rwf, *xf, *of;
    cudaGetSymbolAddress((void**)&qwf, g_qwf);
    cudaGetSymbolAddress((void**)&rwf, g_rwf);
    cudaGetSymbolAddress((void**)&xf, g_xf);
    cudaGetSymbolAddress((void**)&of, g_of);

    // K0: zero g_qkv (atomicAdd target for K-split qkv GEMM)
    cudaMemsetAsync(qkv_ptr, 0, (size_t)NBATCH * 192 * L * sizeof(float));

    // K1a: build A-frags for qkv_w [192x512] and res_w [512x64]
    afrag_split_kernel<<<48, 256>>>(qkv_w, qwf, 512, 32, 12 * 32 * 32);
    afrag_split_kernel<<<16, 256>>>(res_w, rwf, 64, 4, 32 * 4 * 32);
    // K1b: build B-frags for x
    {
        int total = NBATCH * NCB * 32 * 32;
        bfrag_split_kernel<<<(total + 255) / 256, 256>>>(x, xf, 512, 32, total);
    }
    // K1c: qkv GEMM (split-f16 HMMA, K-split 2x, atomicAdd) -> g_qkv
    hgemm_split_kernel<<<dim3(18, 12, NBATCH), 256>>>(
        qwf, xf, qkv_b, qkv_ptr, 192, 32, 2, 1);

    // K2: attention fragment images
    {
        int total = NT_Q + NT_K + NT_V;
        convert_kernel<<<(total + 255) / 256, 256>>>();
    }

    // K3: attention (HMMA tensor cores)
    attn_hmma_kernel<<<NNH * NQT, 256>>>();

    // K4: pos conv (K-split 4x, atomicAdd into g_o)
    pos_gemm_kernel<<<dim3(72, 4, NBATCH), 256>>>(pos_w, pos_b);

    // K5a: build B-frags for attention+pos output
    {
        int total = NBATCH * NCB * 4 * 32;
        bfrag_split_kernel<<<(total + 255) / 256, 256>>>(o_ptr, of, 64, 4, total);
    }
    // K5b: res GEMM (split-f16 HMMA) -> out
    hgemm_split_kernel<<<dim3(18, 16, NBATCH), 256>>>(
        rwf, of, res_b, out, 512, 4, 1, 0);
}